// round 1
// baseline (speedup 1.0000x reference)
#include <cuda_runtime.h>
#include <cuda_bf16.h>
#include <cstdint>

// Problem shape (fixed for this dataset entry)
#define M_TOTAL 8192      // B*S = 4*2048
#define N_TOTAL 4096      // OUT
#define K_TOTAL 4096      // IN
#define K2      8192      // hi|lo doubled K

// Scratch: A packed as [M][K2] bf16 where cols [0,4096) = hi(x), [4096,8192) = lo(x).
// B packed as [N][K] bf16 of the raw int4 weight values (exact in bf16).
__device__ __nv_bfloat16 g_A[(size_t)M_TOTAL * K2];        // 128 MB
__device__ __nv_bfloat16 g_Bw[(size_t)N_TOTAL * K_TOTAL];  // 32 MB

// ---------------------------------------------------------------------------
// Prep kernels
// ---------------------------------------------------------------------------
__global__ void __launch_bounds__(256) prep_a_kernel(const float4* __restrict__ x4) {
    size_t i = (size_t)blockIdx.x * 256 + threadIdx.x;   // float4 index
    float4 v = x4[i];
    size_t e = i << 2;
    size_t m = e >> 12;        // /4096
    size_t k = e & 4095;

    __nv_bfloat16 h0 = __float2bfloat16(v.x);
    __nv_bfloat16 h1 = __float2bfloat16(v.y);
    __nv_bfloat16 h2 = __float2bfloat16(v.z);
    __nv_bfloat16 h3 = __float2bfloat16(v.w);
    __nv_bfloat16 l0 = __float2bfloat16(v.x - __bfloat162float(h0));
    __nv_bfloat16 l1 = __float2bfloat16(v.y - __bfloat162float(h1));
    __nv_bfloat16 l2 = __float2bfloat16(v.z - __bfloat162float(h2));
    __nv_bfloat16 l3 = __float2bfloat16(v.w - __bfloat162float(h3));

    __nv_bfloat162 t;
    __nv_bfloat162* hp = (__nv_bfloat162*)(g_A + m * K2 + k);
    t.x = h0; t.y = h1; hp[0] = t;
    t.x = h2; t.y = h3; hp[1] = t;
    __nv_bfloat162* lp = (__nv_bfloat162*)(g_A + m * K2 + (size_t)K_TOTAL + k);
    t.x = l0; t.y = l1; lp[0] = t;
    t.x = l2; t.y = l3; lp[1] = t;
}

__global__ void __launch_bounds__(256) prep_b_kernel(const int4* __restrict__ w4) {
    size_t i = (size_t)blockIdx.x * 256 + threadIdx.x;   // int4 (4x int32) index
    int4 q = w4[i];
    __nv_bfloat162 t0, t1;
    t0.x = __float2bfloat16((float)q.x);
    t0.y = __float2bfloat16((float)q.y);
    t1.x = __float2bfloat16((float)q.z);
    t1.y = __float2bfloat16((float)q.w);
    __nv_bfloat162* bp = (__nv_bfloat162*)(g_Bw) + i * 2;
    bp[0] = t0;
    bp[1] = t1;
}

// ---------------------------------------------------------------------------
// GEMM: C[m,n] = sum_{k<8192} A[m,k] * B[n, k & 4095]; out = scale[n]*C + bias[n]
// CTA tile 128x128, K-tile 32, 8 warps (2 M x 4 N), warp tile 64x32.
// ---------------------------------------------------------------------------
#define BM 128
#define BN 128
#define BK 32
#define NTILES (K2 / BK)   // 256

__device__ __forceinline__ uint32_t smem_u32(const void* p) {
    return (uint32_t)__cvta_generic_to_shared(p);
}
__device__ __forceinline__ void cp_async16(uint32_t dst, const void* src) {
    asm volatile("cp.async.cg.shared.global [%0], [%1], 16;\n" :: "r"(dst), "l"(src));
}
__device__ __forceinline__ void ldm_x4(uint32_t& d0, uint32_t& d1, uint32_t& d2, uint32_t& d3, uint32_t a) {
    asm volatile("ldmatrix.sync.aligned.m8n8.x4.shared.b16 {%0,%1,%2,%3}, [%4];\n"
                 : "=r"(d0), "=r"(d1), "=r"(d2), "=r"(d3) : "r"(a));
}
__device__ __forceinline__ void ldm_x2(uint32_t& d0, uint32_t& d1, uint32_t a) {
    asm volatile("ldmatrix.sync.aligned.m8n8.x2.shared.b16 {%0,%1}, [%2];\n"
                 : "=r"(d0), "=r"(d1) : "r"(a));
}
__device__ __forceinline__ void mma16816(float* c, const uint32_t* a, const uint32_t* b) {
    asm volatile(
        "mma.sync.aligned.m16n8k16.row.col.f32.bf16.bf16.f32 "
        "{%0,%1,%2,%3}, {%4,%5,%6,%7}, {%8,%9}, {%0,%1,%2,%3};\n"
        : "+f"(c[0]), "+f"(c[1]), "+f"(c[2]), "+f"(c[3])
        : "r"(a[0]), "r"(a[1]), "r"(a[2]), "r"(a[3]), "r"(b[0]), "r"(b[1]));
}

__global__ void __launch_bounds__(256)
gemm_bf16_kernel(const float* __restrict__ wscale, const float* __restrict__ bias,
                 float* __restrict__ out)
{
    __shared__ __align__(1024) __nv_bfloat16 As[2][BM * BK];
    __shared__ __align__(1024) __nv_bfloat16 Bs[2][BM * BK];

    const int tid  = threadIdx.x;
    const int lane = tid & 31;
    const int warp = tid >> 5;
    const int wm   = warp >> 2;   // 0..1
    const int wn   = warp & 3;    // 0..3
    const int bm   = blockIdx.y * BM;
    const int bn   = blockIdx.x * BN;

    // ---- global -> smem load mapping (2 x 16B chunks per thread per array)
    const int r  = tid >> 2;          // 0..63 (second chunk: r+64)
    const int c  = tid & 3;           // k-chunk (8 bf16 each)
    const int swz = (r >> 1) & 3;     // same for r and r+64
    const uint32_t soff = (uint32_t)r * 64 + (uint32_t)((c ^ swz) << 4);

    const uint32_t sAbase = smem_u32(&As[0][0]);
    const uint32_t sBbase = smem_u32(&Bs[0][0]);

    const __nv_bfloat16* gA = g_A  + (size_t)(bm + r) * K2      + c * 8;
    const __nv_bfloat16* gB = g_Bw + (size_t)(bn + r) * K_TOTAL + c * 8;

    // ---- ldmatrix per-lane address precompute
    // A frags: 4 per warp (m = wm*64 + f*16)
    uint32_t a_rowoff[4], a_swz[4];
    const int a_kg = lane >> 4;            // 0/1 -> k-group 0/8
    #pragma unroll
    for (int f = 0; f < 4; f++) {
        int row = wm * 64 + f * 16 + (lane & 15);
        a_rowoff[f] = (uint32_t)row * 64;
        a_swz[f]    = (row >> 1) & 3;
    }
    // B frags: 4 per warp (n = wn*32 + g*8)
    uint32_t b_rowoff[4], b_swz[4];
    const int b_kg = (lane >> 3) & 1;
    #pragma unroll
    for (int g = 0; g < 4; g++) {
        int row = wn * 32 + g * 8 + (lane & 7);
        b_rowoff[g] = (uint32_t)row * 64;
        b_swz[g]    = (row >> 1) & 3;
    }

    float acc[4][4][4];
    #pragma unroll
    for (int f = 0; f < 4; f++)
        #pragma unroll
        for (int g = 0; g < 4; g++)
            #pragma unroll
            for (int e = 0; e < 4; e++) acc[f][g][e] = 0.f;

    // ---- prologue: load tile 0
    {
        const int k = 0;
        cp_async16(sAbase + soff,            gA + k);
        cp_async16(sAbase + soff + 4096,     gA + (size_t)64 * K2 + k);
        cp_async16(sBbase + soff,            gB + k);
        cp_async16(sBbase + soff + 4096,     gB + (size_t)64 * K_TOTAL + k);
        asm volatile("cp.async.commit_group;\n");
        asm volatile("cp.async.wait_group 0;\n");
        __syncthreads();
    }

    for (int kt = 0; kt < NTILES; kt++) {
        const int buf = kt & 1;
        if (kt + 1 < NTILES) {
            const int knext = (kt + 1) * BK;
            const int keff  = knext & (K_TOTAL - 1);
            const uint32_t dA = sAbase + (uint32_t)((kt + 1) & 1) * 8192;
            const uint32_t dB = sBbase + (uint32_t)((kt + 1) & 1) * 8192;
            cp_async16(dA + soff,        gA + knext);
            cp_async16(dA + soff + 4096, gA + (size_t)64 * K2 + knext);
            cp_async16(dB + soff,        gB + keff);
            cp_async16(dB + soff + 4096, gB + (size_t)64 * K_TOTAL + keff);
            asm volatile("cp.async.commit_group;\n");
        }

        const uint32_t sAbuf = sAbase + (uint32_t)buf * 8192;
        const uint32_t sBbuf = sBbase + (uint32_t)buf * 8192;

        #pragma unroll
        for (int ks = 0; ks < 2; ks++) {
            uint32_t a[4][4];
            #pragma unroll
            for (int f = 0; f < 4; f++) {
                uint32_t chunk = (uint32_t)(ks * 2 + a_kg) ^ a_swz[f];
                ldm_x4(a[f][0], a[f][1], a[f][2], a[f][3],
                       sAbuf + a_rowoff[f] + (chunk << 4));
            }
            uint32_t b[4][2];
            #pragma unroll
            for (int g = 0; g < 4; g++) {
                uint32_t chunk = (uint32_t)(ks * 2 + b_kg) ^ b_swz[g];
                ldm_x2(b[g][0], b[g][1],
                       sBbuf + b_rowoff[g] + (chunk << 4));
            }
            #pragma unroll
            for (int f = 0; f < 4; f++)
                #pragma unroll
                for (int g = 0; g < 4; g++)
                    mma16816(acc[f][g], a[f], b[g]);
        }

        if (kt + 1 < NTILES) {
            asm volatile("cp.async.wait_group 0;\n");
            __syncthreads();
        }
    }

    // ---- epilogue: out = scale[n]*acc + bias[n]
    const int mrow  = bm + wm * 64 + (lane >> 2);
    const int ncol0 = bn + wn * 32 + (lane & 3) * 2;

    float2 sc[4], bi[4];
    #pragma unroll
    for (int g = 0; g < 4; g++) {
        int col = ncol0 + g * 8;
        sc[g].x = wscale[col]; sc[g].y = wscale[col + 1];
        bi[g].x = bias[col];   bi[g].y = bias[col + 1];
    }

    #pragma unroll
    for (int f = 0; f < 4; f++) {
        int r0 = mrow + f * 16;
        #pragma unroll
        for (int g = 0; g < 4; g++) {
            int col = ncol0 + g * 8;
            float2 v0, v1;
            v0.x = acc[f][g][0] * sc[g].x + bi[g].x;
            v0.y = acc[f][g][1] * sc[g].y + bi[g].y;
            v1.x = acc[f][g][2] * sc[g].x + bi[g].x;
            v1.y = acc[f][g][3] * sc[g].y + bi[g].y;
            *(float2*)(out + (size_t)r0 * N_TOTAL + col)       = v0;
            *(float2*)(out + (size_t)(r0 + 8) * N_TOTAL + col) = v1;
        }
    }
}

// ---------------------------------------------------------------------------
extern "C" void kernel_launch(void* const* d_in, const int* in_sizes, int n_in,
                              void* d_out, int out_size) {
    const float* x      = (const float*)d_in[0];
    const int*   wq     = (const int*)d_in[1];
    const float* wscale = (const float*)d_in[2];
    const float* bias   = (const float*)d_in[3];
    float*       out    = (float*)d_out;

    // x -> hi/lo bf16 pack
    prep_a_kernel<<<(M_TOTAL * (size_t)K_TOTAL / 4) / 256, 256>>>((const float4*)x);
    // weight int32 -> bf16 (exact)
    prep_b_kernel<<<(N_TOTAL * (size_t)K_TOTAL / 4) / 256, 256>>>((const int4*)wq);

    dim3 grid(N_TOTAL / BN, M_TOTAL / BM);
    gemm_bf16_kernel<<<grid, 256>>>(wscale, bias, out);
}

// round 3
// speedup vs baseline: 3.0236x; 3.0236x over previous
#include <cuda_runtime.h>
#include <cuda_bf16.h>
#include <cuda_fp16.h>
#include <cstdint>

#define M_TOTAL 8192
#define N_TOTAL 4096
#define K_TOTAL 4096

// fp16 operands: A = fp16(x) [M][K], B = exact int4 values in fp16 [N][K]
__device__ __half g_A[(size_t)M_TOTAL * K_TOTAL];   // 64 MB
__device__ __half g_B[(size_t)N_TOTAL * K_TOTAL];   // 32 MB

// ---------------------------------------------------------------------------
// Prep kernels (pure streaming conversions)
// ---------------------------------------------------------------------------
__global__ void __launch_bounds__(256) prep_a_kernel(const float4* __restrict__ x4) {
    size_t i = (size_t)blockIdx.x * 256 + threadIdx.x;
    float4 v = x4[i];
    __half2* dst = (__half2*)g_A + i * 2;
    dst[0] = __floats2half2_rn(v.x, v.y);
    dst[1] = __floats2half2_rn(v.z, v.w);
}

__global__ void __launch_bounds__(256) prep_b_kernel(const int4* __restrict__ w4) {
    size_t i = (size_t)blockIdx.x * 256 + threadIdx.x;
    int4 q = w4[i];
    __half2* dst = (__half2*)g_B + i * 2;
    dst[0] = __floats2half2_rn((float)q.x, (float)q.y);
    dst[1] = __floats2half2_rn((float)q.z, (float)q.w);
}

// ---------------------------------------------------------------------------
// Common helpers
// ---------------------------------------------------------------------------
__device__ __forceinline__ uint32_t smem_u32(const void* p) {
    uint32_t a;
    asm("{ .reg .u64 t; cvta.to.shared.u64 t, %1; cvt.u32.u64 %0, t; }" : "=r"(a) : "l"(p));
    return a;
}
__device__ __forceinline__ void cp_async16(uint32_t dst, const void* src) {
    asm volatile("cp.async.cg.shared.global [%0], [%1], 16;\n" :: "r"(dst), "l"(src));
}

#define STAGES 4
#define SMEM_BYTES 100352

// ===========================================================================
#if defined(__CUDA_ARCH__) && defined(__CUDA_ARCH_FEAT_SM103_ALL)
// tcgen05 path helpers (only legal when virtual arch is compute_103a)
// ===========================================================================
#define HAVE_TCGEN05 1

__device__ __forceinline__ uint32_t elect_one_pred() {
    uint32_t pred;
    asm volatile("{\n\t.reg .pred p;\n\telect.sync _|p, 0xFFFFFFFF;\n\tselp.b32 %0, 1, 0, p;\n\t}"
                 : "=r"(pred));
    return pred;
}
__device__ __forceinline__ uint32_t cluster_rank() {
    uint32_t r;
    asm("mov.u32 %0, %%cluster_ctarank;" : "=r"(r));
    return r;
}

#define MBARRIER_INIT(addr, count) \
    asm volatile("mbarrier.init.shared.b64 [%0], %1;" :: "r"(addr), "r"(count) : "memory")
#define MBARRIER_ARRIVE_CLUSTER(addr, rnk) \
    asm volatile("{\n\t.reg .b32 rem;\n\tmapa.shared::cluster.u32 rem, %0, %1;\n\t" \
                 "mbarrier.arrive.shared::cluster.b64 _, [rem];\n\t}" \
                 :: "r"(addr), "r"(rnk) : "memory")
#define MBARRIER_WAIT_PARITY(addr, parity) do { \
    uint32_t _m = (addr); uint32_t _p = (parity); uint32_t _d; \
    asm volatile("{\n\t.reg .pred p;\n\t" \
        "mbarrier.try_wait.parity.acquire.cta.shared::cta.b64 p, [%1], %2;\n\t" \
        "selp.b32 %0, 1, 0, p;\n\t}" : "=r"(_d) : "r"(_m), "r"(_p) : "memory"); \
    if (!_d) { \
        asm volatile("{\n\t.reg .pred P1;\n\t" \
            "WL_%=:\n\t" \
            "mbarrier.try_wait.parity.acquire.cta.shared::cta.b64 P1, [%0], %1, 0x989680;\n\t" \
            "@P1 bra.uni WD_%=;\n\tbra.uni WL_%=;\n\tWD_%=:\n\t}" \
            :: "r"(_m), "r"(_p) : "memory"); \
    } \
} while (0)
#define CLUSTER_SYNC() do { \
    asm volatile("barrier.cluster.arrive.aligned;" ::: "memory"); \
    asm volatile("barrier.cluster.wait.aligned;" ::: "memory"); \
} while (0)
#define TCGEN05_ALLOC_CG2(smem_addr, ncols) \
    asm volatile("tcgen05.alloc.cta_group::2.sync.aligned.shared::cta.b32 [%0], %1;" \
                 :: "r"((uint32_t)(smem_addr)), "r"((uint32_t)(ncols)) : "memory")
#define TCGEN05_DEALLOC_CG2(tmem, ncols) \
    asm volatile("tcgen05.dealloc.cta_group::2.sync.aligned.b32 %0, %1;" :: "r"(tmem), "r"(ncols))
#define TCGEN05_RELINQUISH_CG2() \
    asm volatile("tcgen05.relinquish_alloc_permit.cta_group::2.sync.aligned;")
#define TCGEN05_COMMIT_MC_CG2(mbar, mask) \
    asm volatile("tcgen05.commit.cta_group::2.mbarrier::arrive::one.shared::cluster.multicast::cluster.b64 [%0], %1;" \
                 :: "r"((uint32_t)(mbar)), "h"((uint16_t)(mask)) : "memory")
#define TCGEN05_FENCE_AFTER()  asm volatile("tcgen05.fence::after_thread_sync;" ::: "memory")
#define TCGEN05_FENCE_BEFORE() asm volatile("tcgen05.fence::before_thread_sync;" ::: "memory")
#define TCGEN05_WAIT_LD()      asm volatile("tcgen05.wait::ld.sync.aligned;" ::: "memory")

#define TCGEN05_LD_32X32B_X32(r, tmem_addr) \
    asm volatile( \
        "tcgen05.ld.sync.aligned.32x32b.x32.b32 " \
        "{%0, %1, %2, %3, %4, %5, %6, %7, " \
        " %8, %9, %10, %11, %12, %13, %14, %15, " \
        " %16, %17, %18, %19, %20, %21, %22, %23, " \
        " %24, %25, %26, %27, %28, %29, %30, %31}, [%32];" \
        : "=r"((r)[0]),  "=r"((r)[1]),  "=r"((r)[2]),  "=r"((r)[3]), \
          "=r"((r)[4]),  "=r"((r)[5]),  "=r"((r)[6]),  "=r"((r)[7]), \
          "=r"((r)[8]),  "=r"((r)[9]),  "=r"((r)[10]), "=r"((r)[11]), \
          "=r"((r)[12]), "=r"((r)[13]), "=r"((r)[14]), "=r"((r)[15]), \
          "=r"((r)[16]), "=r"((r)[17]), "=r"((r)[18]), "=r"((r)[19]), \
          "=r"((r)[20]), "=r"((r)[21]), "=r"((r)[22]), "=r"((r)[23]), \
          "=r"((r)[24]), "=r"((r)[25]), "=r"((r)[26]), "=r"((r)[27]), \
          "=r"((r)[28]), "=r"((r)[29]), "=r"((r)[30]), "=r"((r)[31]) \
        : "r"(tmem_addr))

__device__ __forceinline__ void mma_f16_ss_cg2(
    uint32_t d_tmem, uint64_t a_desc, uint64_t b_desc, uint32_t idesc, bool en_d)
{
    uint32_t en = en_d ? 1u : 0u;
    asm volatile(
        "{\n\t.reg .pred p;\n\tsetp.ne.u32 p, %6, 0;\n\t"
        "tcgen05.mma.cta_group::2.kind::f16 [%0], %1, %2, %3, "
        "{%4, %4, %4, %4, %4, %4, %4, %4}, p;\n\t}"
        :: "r"(d_tmem), "l"(a_desc), "l"(b_desc), "r"(idesc),
           "r"(0u), "r"(0u), "r"(en)
        : "memory");
}

// SW128 K-major descriptor base
static constexpr uint64_t DESC_BASE =
    (uint64_t(2) << 61) | (uint64_t(1) << 46) | (uint64_t(64) << 32) | (uint64_t(1) << 16);

#else
#define HAVE_TCGEN05 0
#endif

// ---------------------------------------------------------------------------
// fallback mma.sync helpers
// ---------------------------------------------------------------------------
__device__ __forceinline__ void ldm_x4(uint32_t& d0, uint32_t& d1, uint32_t& d2, uint32_t& d3, uint32_t a) {
    asm volatile("ldmatrix.sync.aligned.m8n8.x4.shared.b16 {%0,%1,%2,%3}, [%4];\n"
                 : "=r"(d0), "=r"(d1), "=r"(d2), "=r"(d3) : "r"(a));
}
__device__ __forceinline__ void ldm_x2(uint32_t& d0, uint32_t& d1, uint32_t a) {
    asm volatile("ldmatrix.sync.aligned.m8n8.x2.shared.b16 {%0,%1}, [%2];\n"
                 : "=r"(d0), "=r"(d1) : "r"(a));
}
__device__ __forceinline__ void mma16816(float* c, const uint32_t* a, const uint32_t* b) {
    asm volatile(
        "mma.sync.aligned.m16n8k16.row.col.f32.f16.f16.f32 "
        "{%0,%1,%2,%3}, {%4,%5,%6,%7}, {%8,%9}, {%0,%1,%2,%3};\n"
        : "+f"(c[0]), "+f"(c[1]), "+f"(c[2]), "+f"(c[3])
        : "r"(a[0]), "r"(a[1]), "r"(a[2]), "r"(a[3]), "r"(b[0]), "r"(b[1]));
}

// ===========================================================================
// Unified GEMM kernel. Grid (2, 32, 32), cluster (2,1,1), 256 threads.
//   tcgen05 path:  pair tile 256M x 128N per cluster
//   fallback path: 128M x 128N per CTA (bm = z*256 + x*128, bn = y*128)
// ===========================================================================
__global__ void __launch_bounds__(256) __cluster_dims__(2, 1, 1)
gemm_kernel(const float* __restrict__ wscale, const float* __restrict__ bias,
            float* __restrict__ out)
{
    extern __shared__ char smem_raw[];
    const uint32_t base = (smem_u32(smem_raw) + 1023u) & ~1023u;
    const int tid = threadIdx.x;

#if HAVE_TCGEN05
    // ------------------------- tcgen05 cg2 path ---------------------------
    #define BK 64
    #define NITER (K_TOTAL / BK)          // 64
    #define A_STAGE 16384                 // 128 rows x 128B
    #define B_STAGE 8192                  // 64 rows x 128B
    const uint32_t sA = base;
    const uint32_t sB = base + STAGES * A_STAGE;
    const uint32_t fullBar  = sB + STAGES * B_STAGE;
    const uint32_t doneBar  = fullBar + STAGES * 8;
    const uint32_t finalBar = doneBar + STAGES * 8;
    const uint32_t tmemPtr  = finalBar + 8;

    const uint32_t rank = cluster_rank();
    const int bn = blockIdx.y * 128;
    const int m0 = blockIdx.z * 256 + (int)rank * 128;
    const int n0 = bn + (int)rank * 64;

    // idesc: dtype F32, a/b FP16, N=128, M=256
    const uint32_t IDESC = (1u << 4) | ((128u / 8) << 17) | ((256u / 16) << 24);

    if (tid == 0) {
        #pragma unroll
        for (int s = 0; s < STAGES; s++) {
            MBARRIER_INIT(fullBar + s * 8, 2);
            MBARRIER_INIT(doneBar + s * 8, 1);
        }
        MBARRIER_INIT(finalBar, 1);
    }
    if (tid < 32) TCGEN05_ALLOC_CG2(tmemPtr, 512);
    __syncthreads();
    CLUSTER_SYNC();

    uint32_t tmem;
    asm volatile("ld.shared.b32 %0, [%1];" : "=r"(tmem) : "r"(tmemPtr));

    const int row0 = tid >> 3;   // 0..31
    const int kc   = tid & 7;
    uint32_t swoff[4];
    #pragma unroll
    for (int j = 0; j < 4; j++) {
        uint32_t o = (uint32_t)(row0 + 32 * j) * 128 + (uint32_t)kc * 16;
        swoff[j] = o ^ ((o >> 3) & 0x70);
    }
    const __half* gA = g_A + (size_t)(m0 + row0) * K_TOTAL + kc * 8;
    const __half* gB = g_B + (size_t)(n0 + row0) * K_TOTAL + kc * 8;

    for (int i = 0; i < NITER + STAGES - 1; i++) {
        if (i < NITER) {
            const int slot = i & (STAGES - 1);
            if (i >= STAGES)
                MBARRIER_WAIT_PARITY(doneBar + slot * 8, ((i / STAGES) + 1) & 1);
            const uint32_t dA = sA + slot * A_STAGE;
            const uint32_t dB = sB + slot * B_STAGE;
            const __half* pA = gA + (size_t)i * BK;
            const __half* pB = gB + (size_t)i * BK;
            #pragma unroll
            for (int j = 0; j < 4; j++)
                cp_async16(dA + swoff[j], pA + (size_t)(32 * j) * K_TOTAL);
            #pragma unroll
            for (int j = 0; j < 2; j++)
                cp_async16(dB + swoff[j], pB + (size_t)(32 * j) * K_TOTAL);
        }
        asm volatile("cp.async.commit_group;\n" ::: "memory");

        const int c = i - (STAGES - 1);
        if (c >= 0) {
            asm volatile("cp.async.wait_group 3;\n" ::: "memory");
            asm volatile("fence.proxy.async.shared::cta;" ::: "memory");
            __syncthreads();
            const int slot = c & (STAGES - 1);
            if (tid == 0)
                MBARRIER_ARRIVE_CLUSTER(fullBar + slot * 8, 0);
            if (rank == 0 && tid < 32) {
                if (elect_one_pred()) {
                    MBARRIER_WAIT_PARITY(fullBar + slot * 8, (c / STAGES) & 1);
                    uint64_t a_desc = DESC_BASE | (((uint64_t)((sA + slot * A_STAGE) >> 4)) & 0x3FFF);
                    uint64_t b_desc = DESC_BASE | (((uint64_t)((sB + slot * B_STAGE) >> 4)) & 0x3FFF);
                    #pragma unroll
                    for (int k4 = 0; k4 < 4; k4++)
                        mma_f16_ss_cg2(tmem, a_desc + k4 * 2, b_desc + k4 * 2, IDESC,
                                       (c > 0) || (k4 > 0));
                    TCGEN05_COMMIT_MC_CG2(doneBar + slot * 8, 0x3);
                }
            }
        }
    }

    if (rank == 0 && tid < 32) {
        if (elect_one_pred()) TCGEN05_COMMIT_MC_CG2(finalBar, 0x3);
    }
    MBARRIER_WAIT_PARITY(finalBar, 0);
    TCGEN05_FENCE_AFTER();

    const int w = tid >> 5, lid = tid & 31;
    if (w < 4) {
        const int mrow = m0 + w * 32 + lid;
        float* orow = out + (size_t)mrow * N_TOTAL + bn;
        #pragma unroll
        for (int ch = 0; ch < 4; ch++) {
            uint32_t r[32];
            TCGEN05_LD_32X32B_X32(r, tmem + ch * 32);
            TCGEN05_WAIT_LD();
            const int c0 = ch * 32;
            #pragma unroll
            for (int q = 0; q < 8; q++) {
                const int cc = c0 + q * 4;
                float4 v;
                v.x = __uint_as_float(r[q * 4 + 0]) * wscale[bn + cc + 0] + bias[bn + cc + 0];
                v.y = __uint_as_float(r[q * 4 + 1]) * wscale[bn + cc + 1] + bias[bn + cc + 1];
                v.z = __uint_as_float(r[q * 4 + 2]) * wscale[bn + cc + 2] + bias[bn + cc + 2];
                v.w = __uint_as_float(r[q * 4 + 3]) * wscale[bn + cc + 3] + bias[bn + cc + 3];
                *(float4*)(orow + cc) = v;
            }
        }
    }
    TCGEN05_FENCE_BEFORE();
    __syncthreads();
    if (tid < 32) {
        TCGEN05_RELINQUISH_CG2();
        TCGEN05_DEALLOC_CG2(tmem, 512);
    }
    CLUSTER_SYNC();
    #undef BK
    #undef NITER
#else
    // ------------------------- mma.sync fallback ---------------------------
    // 128x128 CTA tile, BK=32, 4-stage cp.async, 8 warps (2M x 4N), warp 64x32
    #define BK 32
    #define NITER (K_TOTAL / BK)          // 128
    #define STAGE 8192                    // 128 rows x 64B
    const uint32_t sAbase = base;                      // 4 x 8KB
    const uint32_t sBbase = base + STAGES * STAGE;     // 4 x 8KB

    const int lane = tid & 31;
    const int warp = tid >> 5;
    const int wm   = warp >> 2;
    const int wn   = warp & 3;
    const int bm   = blockIdx.z * 256 + blockIdx.x * 128;
    const int bn   = blockIdx.y * 128;

    const int r  = tid >> 2;          // 0..63
    const int c  = tid & 3;
    const int swz = (r >> 1) & 3;
    const uint32_t soff = (uint32_t)r * 64 + (uint32_t)((c ^ swz) << 4);

    const __half* gA = g_A + (size_t)(bm + r) * K_TOTAL + c * 8;
    const __half* gB = g_B + (size_t)(bn + r) * K_TOTAL + c * 8;

    uint32_t a_rowoff[4], a_swz[4];
    const int a_kg = lane >> 4;
    #pragma unroll
    for (int f = 0; f < 4; f++) {
        int row = wm * 64 + f * 16 + (lane & 15);
        a_rowoff[f] = (uint32_t)row * 64;
        a_swz[f]    = (row >> 1) & 3;
    }
    uint32_t b_rowoff[4], b_swz[4];
    const int b_kg = (lane >> 3) & 1;
    #pragma unroll
    for (int g = 0; g < 4; g++) {
        int row = wn * 32 + g * 8 + (lane & 7);
        b_rowoff[g] = (uint32_t)row * 64;
        b_swz[g]    = (row >> 1) & 3;
    }

    float acc[4][4][4];
    #pragma unroll
    for (int f = 0; f < 4; f++)
        #pragma unroll
        for (int g = 0; g < 4; g++)
            #pragma unroll
            for (int e = 0; e < 4; e++) acc[f][g][e] = 0.f;

    // prologue: fill STAGES-1 slots
    #pragma unroll
    for (int s = 0; s < STAGES - 1; s++) {
        const uint32_t dA = sAbase + s * STAGE;
        const uint32_t dB = sBbase + s * STAGE;
        const int k = s * BK;
        cp_async16(dA + soff,        gA + k);
        cp_async16(dA + soff + 4096, gA + (size_t)64 * K_TOTAL + k);
        cp_async16(dB + soff,        gB + k);
        cp_async16(dB + soff + 4096, gB + (size_t)64 * K_TOTAL + k);
        asm volatile("cp.async.commit_group;\n" ::: "memory");
    }

    for (int kt = 0; kt < NITER; kt++) {
        asm volatile("cp.async.wait_group %0;\n" :: "n"(STAGES - 2) : "memory");
        __syncthreads();

        // prefetch slot kt+STAGES-1
        if (kt + STAGES - 1 < NITER) {
            const int s = (kt + STAGES - 1) & (STAGES - 1);
            const int k = (kt + STAGES - 1) * BK;
            const uint32_t dA = sAbase + s * STAGE;
            const uint32_t dB = sBbase + s * STAGE;
            cp_async16(dA + soff,        gA + k);
            cp_async16(dA + soff + 4096, gA + (size_t)64 * K_TOTAL + k);
            cp_async16(dB + soff,        gB + k);
            cp_async16(dB + soff + 4096, gB + (size_t)64 * K_TOTAL + k);
        }
        asm volatile("cp.async.commit_group;\n" ::: "memory");

        const int slot = kt & (STAGES - 1);
        const uint32_t sAbuf = sAbase + slot * STAGE;
        const uint32_t sBbuf = sBbase + slot * STAGE;

        #pragma unroll
        for (int ks = 0; ks < 2; ks++) {
            uint32_t a[4][4];
            #pragma unroll
            for (int f = 0; f < 4; f++) {
                uint32_t chunk = (uint32_t)(ks * 2 + a_kg) ^ a_swz[f];
                ldm_x4(a[f][0], a[f][1], a[f][2], a[f][3],
                       sAbuf + a_rowoff[f] + (chunk << 4));
            }
            uint32_t b[4][2];
            #pragma unroll
            for (int g = 0; g < 4; g++) {
                uint32_t chunk = (uint32_t)(ks * 2 + b_kg) ^ b_swz[g];
                ldm_x2(b[g][0], b[g][1], sBbuf + b_rowoff[g] + (chunk << 4));
            }
            #pragma unroll
            for (int f = 0; f < 4; f++)
                #pragma unroll
                for (int g = 0; g < 4; g++)
                    mma16816(acc[f][g], a[f], b[g]);
        }
    }

    // epilogue
    const int mrow  = bm + wm * 64 + (lane >> 2);
    const int ncol0 = bn + wn * 32 + (lane & 3) * 2;
    float2 sc[4], bi[4];
    #pragma unroll
    for (int g = 0; g < 4; g++) {
        int col = ncol0 + g * 8;
        sc[g].x = wscale[col]; sc[g].y = wscale[col + 1];
        bi[g].x = bias[col];   bi[g].y = bias[col + 1];
    }
    #pragma unroll
    for (int f = 0; f < 4; f++) {
        int r0 = mrow + f * 16;
        #pragma unroll
        for (int g = 0; g < 4; g++) {
            int col = ncol0 + g * 8;
            float2 v0, v1;
            v0.x = acc[f][g][0] * sc[g].x + bi[g].x;
            v0.y = acc[f][g][1] * sc[g].y + bi[g].y;
            v1.x = acc[f][g][2] * sc[g].x + bi[g].x;
            v1.y = acc[f][g][3] * sc[g].y + bi[g].y;
            *(float2*)(out + (size_t)r0 * N_TOTAL + col)       = v0;
            *(float2*)(out + (size_t)(r0 + 8) * N_TOTAL + col) = v1;
        }
    }
    #undef BK
    #undef NITER
    #undef STAGE
#endif
}

// ---------------------------------------------------------------------------
extern "C" void kernel_launch(void* const* d_in, const int* in_sizes, int n_in,
                              void* d_out, int out_size) {
    const float* x      = (const float*)d_in[0];
    const int*   wq     = (const int*)d_in[1];
    const float* wscale = (const float*)d_in[2];
    const float* bias   = (const float*)d_in[3];
    float*       out    = (float*)d_out;

    prep_a_kernel<<<(M_TOTAL * (size_t)K_TOTAL / 4) / 256, 256>>>((const float4*)x);
    prep_b_kernel<<<(N_TOTAL * (size_t)K_TOTAL / 4) / 256, 256>>>((const int4*)wq);

    cudaFuncSetAttribute(gemm_kernel, cudaFuncAttributeMaxDynamicSharedMemorySize, SMEM_BYTES);
    dim3 grid(2, N_TOTAL / 128, M_TOTAL / 256);   // (2, 32, 32), cluster (2,1,1)
    gemm_kernel<<<grid, 256, SMEM_BYTES>>>(wscale, bias, out);
}